// round 6
// baseline (speedup 1.0000x reference)
#include <cuda_runtime.h>
#include <cstdint>

// 2-layer GRU encoder, fused, warp-specialized, weights-in-registers, f32x2 FMA.
// B=1024 batch rows, T=1024 steps, H1=64, H2=32, input feature dim 1.
// Grid: 128 blocks x 256 threads; each block owns 8 batch rows for all T steps.
// Warps 0-3: layer 1 (producer). Warps 4-7: layer 2 (consumer, 1 step behind).

#define T_STEPS 1024
#define NBATCH  1024
#define H1DIM   64
#define H2DIM   32
#define NB      8      // batch rows per block
#define NTHREADS 256

__device__ __forceinline__ void fma2(uint64_t &acc, uint64_t a, uint64_t b) {
    asm("fma.rn.f32x2 %0, %1, %2, %0;" : "+l"(acc) : "l"(a), "l"(b));
}
__device__ __forceinline__ float hadd2(uint64_t v) {
    float lo, hi;
    asm("mov.b64 {%0,%1}, %2;" : "=f"(lo), "=f"(hi) : "l"(v));
    return lo + hi;
}
__device__ __forceinline__ float sigf(float x) {
    // 1/(1+e^-x); MUFU.EX2-based, ~2 ulp — far more accurate than tanh.approx
    return __fdividef(1.0f, 1.0f + __expf(-x));
}
__device__ __forceinline__ float tanhf_fast(float x) {
    // tanh(x) = 2*sigmoid(2x) - 1 ; safe at both infinities
    return fmaf(2.0f, sigf(2.0f * x), -1.0f);
}
__device__ __forceinline__ void barrier_all() {
    // named barrier: both warp-specialized halves arrive from different call sites
    asm volatile("bar.sync 1, %0;" :: "n"(NTHREADS) : "memory");
}

__global__ void __launch_bounds__(NTHREADS, 1)
gru2_fused_kernel(const float* __restrict__ x,
                  const float* __restrict__ Wih1, const float* __restrict__ Whh1,
                  const float* __restrict__ bih1, const float* __restrict__ bhh1,
                  const float* __restrict__ Wih2, const float* __restrict__ Whh2,
                  const float* __restrict__ bih2, const float* __restrict__ bhh2,
                  float* __restrict__ out)
{
    __shared__ __align__(16) float xs[NB][T_STEPS];      // 32 KB: x slab for this block
    __shared__ __align__(16) float h1s[2][NB][H1DIM];    // double-buffered layer1 state
    __shared__ __align__(16) float h2s[2][NB][H2DIM];    // double-buffered layer2 state

    const int tid = threadIdx.x;
    const int b0  = blockIdx.x * NB;

    // --- load x slab (coalesced float4) + zero h buffers ---
    for (int i = tid; i < NB * T_STEPS / 4; i += NTHREADS) {
        int row = i / (T_STEPS / 4);
        int col = i % (T_STEPS / 4);
        reinterpret_cast<float4*>(xs[row])[col] =
            reinterpret_cast<const float4*>(x + (size_t)(b0 + row) * T_STEPS)[col];
    }
    for (int i = tid; i < 2 * NB * H1DIM; i += NTHREADS) (&h1s[0][0][0])[i] = 0.0f;
    for (int i = tid; i < 2 * NB * H2DIM; i += NTHREADS) (&h2s[0][0][0])[i] = 0.0f;
    __syncthreads();

    if (tid < 128) {
        // ================= LAYER 1 =================
        // thread = (j, kh): j in [0,64), kh in {0,1} splits K=64 into halves.
        // lanes 2m / 2m+1 in a warp are the (kh=0, kh=1) pair -> shfl_xor(1).
        const int kh    = tid & 1;
        const int j     = tid >> 1;
        const int kbase = kh * 32;

        // recurrent weights for rows (j, j+64, j+128), k in [kbase, kbase+32), as f32x2
        uint64_t w1[3][16];
        #pragma unroll
        for (int g = 0; g < 3; g++) {
            const float* row = Whh1 + (size_t)(j + 64 * g) * 64 + kbase;
            #pragma unroll
            for (int p = 0; p < 16; p++)
                w1[g][p] = *reinterpret_cast<const uint64_t*>(row + 2 * p);
        }
        const float wir = Wih1[j], wiz = Wih1[j + 64], win = Wih1[j + 128];
        const float br  = bih1[j]      + bhh1[j];
        const float bz  = bih1[j + 64] + bhh1[j + 64];
        const float bni = bih1[j + 128];
        const float bnh = bhh1[j + 128];

        int rp = 0;
        for (int it = 0; it <= T_STEPS; ++it) {
            if (it < T_STEPS) {
                uint64_t aR[NB], aZ[NB], aN[NB];
                #pragma unroll
                for (int b = 0; b < NB; b++) { aR[b] = 0; aZ[b] = 0; aN[b] = 0; }

                #pragma unroll
                for (int p = 0; p < 16; p++) {
                    #pragma unroll
                    for (int b = 0; b < NB; b++) {
                        uint64_t hv = *reinterpret_cast<const uint64_t*>(
                            &h1s[rp][b][kbase + 2 * p]);
                        fma2(aR[b], w1[0][p], hv);
                        fma2(aZ[b], w1[1][p], hv);
                        fma2(aN[b], w1[2][p], hv);
                    }
                }
                #pragma unroll
                for (int b = 0; b < NB; b++) {
                    float sR = hadd2(aR[b]); sR += __shfl_xor_sync(0xffffffffu, sR, 1);
                    float sZ = hadd2(aZ[b]); sZ += __shfl_xor_sync(0xffffffffu, sZ, 1);
                    float sN = hadd2(aN[b]); sN += __shfl_xor_sync(0xffffffffu, sN, 1);
                    if ((b >> 2) == kh) {        // this thread finalizes 4 batches
                        float xv  = xs[b][it];
                        float r   = sigf(fmaf(wir, xv, sR + br));
                        float z   = sigf(fmaf(wiz, xv, sZ + bz));
                        float gxn = fmaf(win, xv, bni);
                        float n   = tanhf_fast(fmaf(r, sN + bnh, gxn));
                        float ho  = h1s[rp][b][j];
                        h1s[rp ^ 1][b][j] = n + z * (ho - n);
                    }
                }
            }
            barrier_all();
            rp ^= 1;
        }
    } else {
        // ================= LAYER 2 (one step behind) =================
        // thread = (j2, sub): j2 in [0,32), sub in [0,4) splits K1=64 / K2=32 in quarters.
        // lanes 4m..4m+3 in a warp are the sub-quad -> shfl_xor(1), shfl_xor(2).
        const int t2  = tid - 128;
        const int sub = t2 & 3;
        const int j2  = t2 >> 2;
        const int k1b = sub * 16;   // slice of h1 (K=64)
        const int k2b = sub * 8;    // slice of h2 (K=32)

        uint64_t wI[3][8], wH[3][4];
        #pragma unroll
        for (int g = 0; g < 3; g++) {
            const float* ri = Wih2 + (size_t)(j2 + 32 * g) * 64 + k1b;
            #pragma unroll
            for (int p = 0; p < 8; p++)
                wI[g][p] = *reinterpret_cast<const uint64_t*>(ri + 2 * p);
            const float* rh = Whh2 + (size_t)(j2 + 32 * g) * 32 + k2b;
            #pragma unroll
            for (int p = 0; p < 4; p++)
                wH[g][p] = *reinterpret_cast<const uint64_t*>(rh + 2 * p);
        }
        const float br2  = bih2[j2]      + bhh2[j2];
        const float bz2  = bih2[j2 + 32] + bhh2[j2 + 32];
        const float bn2i = bih2[j2 + 64];
        const float bn2h = bhh2[j2 + 64];

        int rp = 0, q = 0;
        for (int it = 0; it <= T_STEPS; ++it) {
            if (it >= 1) {
                // processes timestep it-1: input h1[it-1] = h1s[rp], state h2s[q]
                uint64_t aR[NB], aZ[NB], aNI[NB], aNH[NB];
                #pragma unroll
                for (int b = 0; b < NB; b++) { aR[b]=0; aZ[b]=0; aNI[b]=0; aNH[b]=0; }

                #pragma unroll
                for (int p = 0; p < 8; p++) {
                    #pragma unroll
                    for (int b = 0; b < NB; b++) {
                        uint64_t hv = *reinterpret_cast<const uint64_t*>(
                            &h1s[rp][b][k1b + 2 * p]);
                        fma2(aR[b],  wI[0][p], hv);
                        fma2(aZ[b],  wI[1][p], hv);
                        fma2(aNI[b], wI[2][p], hv);
                    }
                }
                #pragma unroll
                for (int p = 0; p < 4; p++) {
                    #pragma unroll
                    for (int b = 0; b < NB; b++) {
                        uint64_t hv = *reinterpret_cast<const uint64_t*>(
                            &h2s[q][b][k2b + 2 * p]);
                        fma2(aR[b],  wH[0][p], hv);
                        fma2(aZ[b],  wH[1][p], hv);
                        fma2(aNH[b], wH[2][p], hv);
                    }
                }
                #pragma unroll
                for (int b = 0; b < NB; b++) {
                    float sR  = hadd2(aR[b]);
                    sR  += __shfl_xor_sync(0xffffffffu, sR, 1);
                    sR  += __shfl_xor_sync(0xffffffffu, sR, 2);
                    float sZ  = hadd2(aZ[b]);
                    sZ  += __shfl_xor_sync(0xffffffffu, sZ, 1);
                    sZ  += __shfl_xor_sync(0xffffffffu, sZ, 2);
                    float sNI = hadd2(aNI[b]);
                    sNI += __shfl_xor_sync(0xffffffffu, sNI, 1);
                    sNI += __shfl_xor_sync(0xffffffffu, sNI, 2);
                    float sNH = hadd2(aNH[b]);
                    sNH += __shfl_xor_sync(0xffffffffu, sNH, 1);
                    sNH += __shfl_xor_sync(0xffffffffu, sNH, 2);
                    if ((b >> 1) == sub) {       // this thread finalizes 2 batches
                        float r  = sigf(sR + br2);
                        float z  = sigf(sZ + bz2);
                        float n  = tanhf_fast(sNI + bn2i + r * (sNH + bn2h));
                        float ho = h2s[q][b][j2];
                        float hn = n + z * (ho - n);
                        h2s[q ^ 1][b][j2] = hn;
                        if (it == T_STEPS)
                            out[(size_t)(b0 + b) * H2DIM + j2] = hn;
                    }
                }
            }
            barrier_all();
            rp ^= 1;
            q  ^= 1;
        }
    }
}

extern "C" void kernel_launch(void* const* d_in, const int* in_sizes, int n_in,
                              void* d_out, int out_size) {
    const float* x    = (const float*)d_in[0];   // [1024,1024]
    const float* Wih1 = (const float*)d_in[1];   // [192,1]
    const float* Whh1 = (const float*)d_in[2];   // [192,64]
    const float* bih1 = (const float*)d_in[3];   // [192]
    const float* bhh1 = (const float*)d_in[4];   // [192]
    const float* Wih2 = (const float*)d_in[5];   // [96,64]
    const float* Whh2 = (const float*)d_in[6];   // [96,32]
    const float* bih2 = (const float*)d_in[7];   // [96]
    const float* bhh2 = (const float*)d_in[8];   // [96]
    float* out = (float*)d_out;                  // [1024,32]

    gru2_fused_kernel<<<NBATCH / NB, NTHREADS>>>(
        x, Wih1, Whh1, bih1, bhh1, Wih2, Whh2, bih2, bhh2, out);
}